// round 14
// baseline (speedup 1.0000x reference)
#include <cuda_runtime.h>

#define RES 512
#define NBLOBS 2048
#define NSPLIT 4
#define QUART (NBLOBS / NSPLIT)
#define TILE_X 32
#define TILE_Y 16
#define BXD 32
#define BYD 4
#define NT 128           // threads per CTA
#define PPT 4            // pixels per thread (stride BYD rows)
#define QCUT 3.75f       // cutoff in sigma units; exp(-7.03) ~ 8.8e-4
#define KKC 0.84932180f  // sqrt(0.5*log2(e))
#define RAD2 (QCUT * QCUT * KKC * KKC)   // disk radius^2 in whitened frame
#define NPIX (RES * RES * 3)
#define NTILES ((RES / TILE_X) * (RES / TILE_Y))

// Scratch (no allocations allowed).
__device__ float4 g_parm[NBLOBS][4];     // (A,B,C,D)(P,Q,m1,m2)(r,r,g,g)(b,b,c0,2c0)
__device__ float g_part[NSPLIT][NPIX];   // partial images
__device__ unsigned int g_cnt[NTILES];   // zero-init; reset by last arriver

// Packed f32x2 helpers (FFMA2 path — ptxas never emits this from C++).
#define FMA2(acc, g, c) \
    asm("fma.rn.f32x2 %0, %1, %2, %0;" : "+l"(acc) : "l"(g), "l"(c))
#define PACK2(out, lo, hi) \
    asm("mov.b64 %0, {%1, %2};" : "=l"(out) : "f"(lo), "f"(hi))
#define UNPACK2(lo, hi, in) \
    asm("mov.b64 {%0, %1}, %2;" : "=f"(lo), "=f"(hi) : "l"(in))

// ---------------------------------------------------------------------------
// Prep: derive splat constants ONCE per blob (was re-derived 512x in render).
//   a = A*px + B*py + P,  b = C*px + D*py + Q   (whitened frame, kk folded in)
//   g = 2^(-(a^2+b^2));  y-stepping by BYD/RES: t += d; d += dd
// ---------------------------------------------------------------------------
__global__ void splat_prep_kernel(const float* __restrict__ blobs) {
    const int i = blockIdx.x * blockDim.x + threadIdx.x;
    if (i >= NBLOBS) return;
    const float4* __restrict__ b4 = (const float4*)blobs;
    const float4 r0 = b4[i * 2 + 0];
    const float4 r1 = b4[i * 2 + 1];
    const float bx = r0.x, by = r0.y, sx = r0.z, sy = r0.w;

    float s, c;
    __sincosf(r1.x, &s, &c);
    const float isx = __fdividef(KKC, sx);
    const float isy = __fdividef(KKC, sy);
    const float A = c * isx, B = s * isx;
    const float C = -s * isy, D = c * isy;
    const float P = -fmaf(A, bx, B * by);
    const float Q = -fmaf(C, bx, D * by);
    const float dlt = (float)BYD / (float)RES;
    const float da = B * dlt, db = D * dlt;
    const float m1 = -2.0f * da, m2 = -2.0f * db;
    const float c0 = -(da * da + db * db);

    g_parm[i][0] = make_float4(A, B, C, D);
    g_parm[i][1] = make_float4(P, Q, m1, m2);
    g_parm[i][2] = make_float4(r1.y, r1.y, r1.z, r1.z);    // (r,r,g,g)
    g_parm[i][3] = make_float4(r1.w, r1.w, c0, c0 + c0);   // (b,b,c0,2c0)
}

// ---------------------------------------------------------------------------
// Render: one CTA per (32x16 tile, blob-quarter). 128 threads; 4 px/thread.
// Per-batch: prefetch 4 derived float4s, exact disk-vs-box cull in the
// whitened frame, ballot/prefix-compact survivors into shared, 2-way-unrolled
// evaluation with second-difference exponent recurrence and f32x2-packed RGB
// accumulation. Tail: last-arriver CTA per tile fuses the four partials.
// ---------------------------------------------------------------------------
__global__ void __launch_bounds__(NT, 8) splat_render_kernel(float* __restrict__ out) {
    __shared__ float4 sP[NT][4];
    __shared__ int sWarp[NT / 32];
    __shared__ unsigned int sArrive;

    const int tx = threadIdx.x;            // 0..31
    const int ty = threadIdx.y;            // 0..3
    const int tid = ty * BXD + tx;
    const int lane = tid & 31;
    const int wid = tid >> 5;
    const int z = blockIdx.z;
    const int blobBase = z * QUART;
    const int tile = blockIdx.y * gridDim.x + blockIdx.x;

    const int x = blockIdx.x * TILE_X + tx;
    const int y0 = blockIdx.y * TILE_Y + ty;
    const float inv = 1.0f / (float)RES;
    const float px = ((float)x + 0.5f) * inv;
    const float py = ((float)y0 + 0.5f) * inv;

    // Tile center and half-extents in normalized coords.
    const float hx = 0.5f * (float)TILE_X * inv;
    const float hy = 0.5f * (float)TILE_Y * inv;
    const float tcx = (float)blockIdx.x * ((float)TILE_X * inv) + hx;
    const float tcy = (float)blockIdx.y * ((float)TILE_Y * inv) + hy;

    // Packed accumulators: (k0,k1) and (k2,k3) pixel pairs for R,G,B.
    unsigned long long accR01 = 0ull, accR23 = 0ull;
    unsigned long long accG01 = 0ull, accG23 = 0ull;
    unsigned long long accB01 = 0ull, accB23 = 0ull;

    // Prefetch batch 0 derived params.
    float4 q0 = g_parm[blobBase + tid][0];
    float4 q1 = g_parm[blobBase + tid][1];
    float4 q2 = g_parm[blobBase + tid][2];
    float4 q3 = g_parm[blobBase + tid][3];

    for (int base = 0; base < QUART; base += NT) {
        // Exact cull: tile -> interval box in whitened (a,b); keep iff the box
        // intersects the disk a^2+b^2 <= RAD2.
        const float ac = fmaf(q0.x, tcx, fmaf(q0.y, tcy, q1.x));
        const float bc = fmaf(q0.z, tcx, fmaf(q0.w, tcy, q1.y));
        const float ra = fabsf(q0.x) * hx + fabsf(q0.y) * hy;
        const float rb = fabsf(q0.z) * hx + fabsf(q0.w) * hy;
        const float dA = fmaxf(fabsf(ac) - ra, 0.0f);
        const float dB = fmaxf(fabsf(bc) - rb, 0.0f);
        const bool keep = fmaf(dA, dA, dB * dB) <= RAD2;

        const unsigned m = __ballot_sync(0xffffffffu, keep);
        if (lane == 0) sWarp[wid] = __popc(m);
        __syncthreads();

        int off = 0, total = 0;
#pragma unroll
        for (int w = 0; w < NT / 32; ++w) {
            int cw = sWarp[w];
            if (w < wid) off += cw;
            total += cw;
        }

        if (keep) {
            const int slot = off + __popc(m & ((1u << lane) - 1u));
            sP[slot][0] = q0;
            sP[slot][1] = q1;
            sP[slot][2] = q2;
            sP[slot][3] = q3;
        }
        __syncthreads();

        // Prefetch next batch (latency hidden behind the j-loop below).
        const int nb = base + NT;
        if (nb < QUART) {
            const int i2 = blobBase + nb + tid;
            q0 = g_parm[i2][0];
            q1 = g_parm[i2][1];
            q2 = g_parm[i2][2];
            q3 = g_parm[i2][3];
        }

#define PAIR_BODY(J)                                                          \
        {                                                                     \
            const float4 p0 = sP[(J)][0];                                     \
            const float4 p1 = sP[(J)][1];                                     \
            const ulonglong2 pc =                                             \
                *reinterpret_cast<const ulonglong2*>(&sP[(J)][2]);            \
            const ulonglong2 p3 =                                             \
                *reinterpret_cast<const ulonglong2*>(&sP[(J)][3]);            \
            float c0f, ddf;                                                   \
            UNPACK2(c0f, ddf, p3.y);                                          \
            float a = fmaf(p0.x, px, fmaf(p0.y, py, p1.x));                   \
            float b = fmaf(p0.z, px, fmaf(p0.w, py, p1.y));                   \
            float t = fmaf(a, -a, -b * b);                                    \
            float d = fmaf(a, p1.z, fmaf(b, p1.w, c0f));                      \
            float g0, g1, g2, g3;                                             \
            asm("ex2.approx.ftz.f32 %0, %1;" : "=f"(g0) : "f"(t));            \
            t += d; d += ddf;                                                 \
            asm("ex2.approx.ftz.f32 %0, %1;" : "=f"(g1) : "f"(t));            \
            t += d; d += ddf;                                                 \
            asm("ex2.approx.ftz.f32 %0, %1;" : "=f"(g2) : "f"(t));            \
            t += d;                                                           \
            asm("ex2.approx.ftz.f32 %0, %1;" : "=f"(g3) : "f"(t));            \
            unsigned long long G01, G23;                                      \
            PACK2(G01, g0, g1);                                               \
            PACK2(G23, g2, g3);                                               \
            FMA2(accR01, G01, pc.x);                                          \
            FMA2(accR23, G23, pc.x);                                          \
            FMA2(accG01, G01, pc.y);                                          \
            FMA2(accG23, G23, pc.y);                                          \
            FMA2(accB01, G01, p3.x);                                          \
            FMA2(accB23, G23, p3.x);                                          \
        }

        int j = 0;
        for (; j + 2 <= total; j += 2) {
            PAIR_BODY(j)
            PAIR_BODY(j + 1)
        }
        if (j < total) {
            PAIR_BODY(j)
        }
#undef PAIR_BODY

        __syncthreads();  // protect sP / sWarp before next batch rewrites them
    }

    // Unpack accumulators.
    float aR[PPT], aG[PPT], aB[PPT];
    UNPACK2(aR[0], aR[1], accR01);
    UNPACK2(aR[2], aR[3], accR23);
    UNPACK2(aG[0], aG[1], accG01);
    UNPACK2(aG[2], aG[3], accG23);
    UNPACK2(aB[0], aB[1], accB01);
    UNPACK2(aB[2], aB[3], accB23);

    // ---- Fused combine (last-block pattern, no spin; deadlock-free) ----
    {
        int idx = (y0 * RES + x) * 3;
        float* __restrict__ mine = g_part[z];
#pragma unroll
        for (int k = 0; k < PPT; ++k) {
            mine[idx + 0] = aR[k];
            mine[idx + 1] = aG[k];
            mine[idx + 2] = aB[k];
            idx += BYD * RES * 3;
        }
    }
    __threadfence();
    __syncthreads();
    if (tid == 0) sArrive = atomicAdd(&g_cnt[tile], 1u);
    __syncthreads();
    if (sArrive == NSPLIT - 1u) {
        // We are last: all peers' partials are published (L2-resident).
        __threadfence();   // acquire: order peers' data before our reads
        const float* __restrict__ pA = g_part[(z + 1) & (NSPLIT - 1)];
        const float* __restrict__ pB = g_part[(z + 2) & (NSPLIT - 1)];
        const float* __restrict__ pC = g_part[(z + 3) & (NSPLIT - 1)];
        int idx = (y0 * RES + x) * 3;
#pragma unroll
        for (int k = 0; k < PPT; ++k) {
            out[idx + 0] = aR[k] + pA[idx + 0] + (pB[idx + 0] + pC[idx + 0]);
            out[idx + 1] = aG[k] + pA[idx + 1] + (pB[idx + 1] + pC[idx + 1]);
            out[idx + 2] = aB[k] + pA[idx + 2] + (pB[idx + 2] + pC[idx + 2]);
            idx += BYD * RES * 3;
        }
        __syncthreads();
        if (tid == 0) g_cnt[tile] = 0u;    // reset for next graph replay
    }
}

extern "C" void kernel_launch(void* const* d_in, const int* in_sizes, int n_in,
                              void* d_out, int out_size) {
    (void)in_sizes; (void)n_in; (void)out_size;
    const float* blobs = (const float*)d_in[0];
    float* out = (float*)d_out;

    splat_prep_kernel<<<NBLOBS / 256, 256>>>(blobs);
    dim3 grid(RES / TILE_X, RES / TILE_Y, NSPLIT);  // 16 x 32 tiles x 4 quarters
    dim3 block(BXD, BYD);
    splat_render_kernel<<<grid, block>>>(out);
}

// round 15
// speedup vs baseline: 1.3583x; 1.3583x over previous
#include <cuda_runtime.h>

#define RES 512
#define NBLOBS 2048
#define NSPLIT 4
#define QUART (NBLOBS / NSPLIT)
#define TILE_X 32
#define TILE_Y 16
#define BXD 32
#define BYD 4
#define NT 128           // threads per CTA
#define PPT 4            // pixels per thread (stride BYD rows)
#define QCUT 3.5f        // cutoff in sigma units; exp(-6.125) ~ 2.2e-3
#define QCUT2 (QCUT * QCUT)
#define NPIX (RES * RES * 3)
#define NTILES ((RES / TILE_X) * (RES / TILE_Y))

// Scratch (no allocations allowed): partial images + per-tile arrival counters.
__device__ float g_part[NSPLIT][NPIX];
__device__ unsigned int g_cnt[NTILES];   // zero-init at load; reset by last arriver

// Packed f32x2 helpers (FFMA2 path — ptxas never emits this from C++).
#define FMA2(acc, g, c) \
    asm("fma.rn.f32x2 %0, %1, %2, %0;" : "+l"(acc) : "l"(g), "l"(c))
#define PACK2(out, lo, hi) \
    asm("mov.b64 %0, {%1, %2};" : "=l"(out) : "f"(lo), "f"(hi))
#define UNPACK2(lo, hi, in) \
    asm("mov.b64 {%0, %1}, %2;" : "=f"(lo), "=f"(hi) : "l"(in))

// ---------------------------------------------------------------------------
// Render: one CTA per (32x16 tile, blob-quarter). 128 threads; 4 px/thread.
// Per-batch: prefetch raw blob (2 float4), derive splat constants in-register,
// cull via exact disk-vs-box test in the blob's whitened (a,b) frame,
// ballot/prefix-compact survivors into shared (colors pre-duplicated, c0/2c0
// pre-packed), 2-way-unrolled evaluation with a second-difference recurrence
// for the exponent and f32x2-packed RGB accumulation:
//   a = A*px + B*py + P,  b = C*px + D*py + Q   (P,Q fold in the blob center)
//   g = 2^(-(a^2+b^2));  stepping y by BYD/RES: t += d; d += dd
// Tail: last-arriver CTA per tile fuses the four partials and writes out.
// ---------------------------------------------------------------------------
__global__ void __launch_bounds__(NT, 8) splat_render_kernel(
        const float* __restrict__ blobs, float* __restrict__ out) {
    __shared__ float4 sP[NT][4];
    __shared__ int sWarp[NT / 32];
    __shared__ unsigned int sArrive;

    const int tx = threadIdx.x;            // 0..31
    const int ty = threadIdx.y;            // 0..3
    const int tid = ty * BXD + tx;
    const int lane = tid & 31;
    const int wid = tid >> 5;
    const int z = blockIdx.z;
    const int blobBase = z * QUART;
    const int tile = blockIdx.y * gridDim.x + blockIdx.x;

    const int x = blockIdx.x * TILE_X + tx;
    const int y0 = blockIdx.y * TILE_Y + ty;
    const float inv = 1.0f / (float)RES;
    const float px = ((float)x + 0.5f) * inv;
    const float py = ((float)y0 + 0.5f) * inv;

    // Tile center and half-extents in normalized coords.
    const float hx = 0.5f * (float)TILE_X * inv;
    const float hy = 0.5f * (float)TILE_Y * inv;
    const float tcx = (float)blockIdx.x * ((float)TILE_X * inv) + hx;
    const float tcy = (float)blockIdx.y * ((float)TILE_Y * inv) + hy;

    // Packed accumulators: (k0,k1) and (k2,k3) pixel pairs for R,G,B.
    unsigned long long accR01 = 0ull, accR23 = 0ull;
    unsigned long long accG01 = 0ull, accG23 = 0ull;
    unsigned long long accB01 = 0ull, accB23 = 0ull;

    // Prefetch batch 0 raw blob (8 floats).
    const float4* __restrict__ blobs4 = (const float4*)blobs;
    float4 r0 = blobs4[(blobBase + tid) * 2 + 0];
    float4 r1 = blobs4[(blobBase + tid) * 2 + 1];

    for (int base = 0; base < QUART; base += NT) {
        // Derive splat constants for this thread's blob of the current batch.
        const float bx = r0.x, by = r0.y, sx = r0.z, sy = r0.w;
        const float rot = r1.x;
        float s, c;
        __sincosf(rot, &s, &c);
        const float kk = 0.84932180f;                  // sqrt(0.5*log2(e))
        const float isx = __fdividef(kk, sx);
        const float isy = __fdividef(kk, sy);
        const float A = c * isx, B = s * isx;
        const float C = -s * isy, D = c * isy;
        const float P = -fmaf(A, bx, B * by);          // fold center into offset
        const float Q = -fmaf(C, bx, D * by);
        const float dlt = (float)BYD * inv;
        const float da_ = B * dlt, db_ = D * dlt;
        const float m1 = -2.0f * da_, m2 = -2.0f * db_;
        const float c0 = -(da_ * da_ + db_ * db_);

        // Cull: tile -> interval box in (a,b); keep iff the box intersects the
        // disk a^2+b^2 <= (QCUT*kk)^2. Note a,b already carry the kk factor,
        // so the radius in this frame is QCUT*kk.
        const float ac = fmaf(A, tcx, fmaf(B, tcy, P));
        const float bc = fmaf(C, tcx, fmaf(D, tcy, Q));
        const float ra = fabsf(A) * hx + fabsf(B) * hy;
        const float rb = fabsf(C) * hx + fabsf(D) * hy;
        const float dA = fmaxf(fabsf(ac) - ra, 0.0f);
        const float dB = fmaxf(fabsf(bc) - rb, 0.0f);
        const float rad2 = QCUT2 * (kk * kk);
        const bool keep = fmaf(dA, dA, dB * dB) <= rad2;

        const unsigned m = __ballot_sync(0xffffffffu, keep);
        if (lane == 0) sWarp[wid] = __popc(m);
        __syncthreads();

        int off = 0, total = 0;
#pragma unroll
        for (int w = 0; w < NT / 32; ++w) {
            int cw = sWarp[w];
            if (w < wid) off += cw;
            total += cw;
        }

        if (keep) {
            const int slot = off + __popc(m & ((1u << lane) - 1u));
            sP[slot][0] = make_float4(A, B, C, D);
            sP[slot][1] = make_float4(P, Q, m1, m2);
            sP[slot][2] = make_float4(r1.y, r1.y, r1.z, r1.z);       // (r,r,g,g)
            sP[slot][3] = make_float4(r1.w, r1.w, c0, c0 + c0);      // (b,b,c0,2c0)
        }
        __syncthreads();

        // Prefetch next batch's raw blob (latency hidden behind the j-loop).
        const int nb = base + NT;
        if (nb < QUART) {
            const int i2 = blobBase + nb + tid;
            r0 = blobs4[i2 * 2 + 0];
            r1 = blobs4[i2 * 2 + 1];
        }

#define PAIR_BODY(J)                                                          \
        {                                                                     \
            const float4 p0 = sP[(J)][0];                                     \
            const float4 p1 = sP[(J)][1];                                     \
            const ulonglong2 pc =                                             \
                *reinterpret_cast<const ulonglong2*>(&sP[(J)][2]);            \
            const ulonglong2 q3 =                                             \
                *reinterpret_cast<const ulonglong2*>(&sP[(J)][3]);            \
            float c0f, ddf;                                                   \
            UNPACK2(c0f, ddf, q3.y);                                          \
            float a = fmaf(p0.x, px, fmaf(p0.y, py, p1.x));                   \
            float b = fmaf(p0.z, px, fmaf(p0.w, py, p1.y));                   \
            float t = fmaf(a, -a, -b * b);                                    \
            float d = fmaf(a, p1.z, fmaf(b, p1.w, c0f));                      \
            float g0, g1, g2, g3;                                             \
            asm("ex2.approx.ftz.f32 %0, %1;" : "=f"(g0) : "f"(t));            \
            t += d; d += ddf;                                                 \
            asm("ex2.approx.ftz.f32 %0, %1;" : "=f"(g1) : "f"(t));            \
            t += d; d += ddf;                                                 \
            asm("ex2.approx.ftz.f32 %0, %1;" : "=f"(g2) : "f"(t));            \
            t += d;                                                           \
            asm("ex2.approx.ftz.f32 %0, %1;" : "=f"(g3) : "f"(t));            \
            unsigned long long G01, G23;                                      \
            PACK2(G01, g0, g1);                                               \
            PACK2(G23, g2, g3);                                               \
            FMA2(accR01, G01, pc.x);                                          \
            FMA2(accR23, G23, pc.x);                                          \
            FMA2(accG01, G01, pc.y);                                          \
            FMA2(accG23, G23, pc.y);                                          \
            FMA2(accB01, G01, q3.x);                                          \
            FMA2(accB23, G23, q3.x);                                          \
        }

        int j = 0;
        for (; j + 2 <= total; j += 2) {
            PAIR_BODY(j)
            PAIR_BODY(j + 1)
        }
        if (j < total) {
            PAIR_BODY(j)
        }
#undef PAIR_BODY

        __syncthreads();  // protect sP / sWarp before next batch rewrites them
    }

    // Unpack accumulators.
    float aR[PPT], aG[PPT], aB[PPT];
    UNPACK2(aR[0], aR[1], accR01);
    UNPACK2(aR[2], aR[3], accR23);
    UNPACK2(aG[0], aG[1], accG01);
    UNPACK2(aG[2], aG[3], accG23);
    UNPACK2(aB[0], aB[1], accB01);
    UNPACK2(aB[2], aB[3], accB23);

    // ---- Fused combine (last-block pattern, no spin; deadlock-free) ----
    {
        int idx = (y0 * RES + x) * 3;
        float* __restrict__ mine = g_part[z];
#pragma unroll
        for (int k = 0; k < PPT; ++k) {
            mine[idx + 0] = aR[k];
            mine[idx + 1] = aG[k];
            mine[idx + 2] = aB[k];
            idx += BYD * RES * 3;
        }
    }
    __threadfence();
    __syncthreads();
    if (tid == 0) sArrive = atomicAdd(&g_cnt[tile], 1u);
    __syncthreads();
    if (sArrive == NSPLIT - 1u) {
        // We are last: all peers' partials are published (L2-resident).
        __threadfence();   // acquire: order peers' data before our reads
        const float* __restrict__ pA = g_part[(z + 1) & (NSPLIT - 1)];
        const float* __restrict__ pB = g_part[(z + 2) & (NSPLIT - 1)];
        const float* __restrict__ pC = g_part[(z + 3) & (NSPLIT - 1)];
        int idx = (y0 * RES + x) * 3;
#pragma unroll
        for (int k = 0; k < PPT; ++k) {
            out[idx + 0] = aR[k] + pA[idx + 0] + (pB[idx + 0] + pC[idx + 0]);
            out[idx + 1] = aG[k] + pA[idx + 1] + (pB[idx + 1] + pC[idx + 1]);
            out[idx + 2] = aB[k] + pA[idx + 2] + (pB[idx + 2] + pC[idx + 2]);
            idx += BYD * RES * 3;
        }
        __syncthreads();
        if (tid == 0) g_cnt[tile] = 0u;    // reset for next graph replay
    }
}

extern "C" void kernel_launch(void* const* d_in, const int* in_sizes, int n_in,
                              void* d_out, int out_size) {
    (void)in_sizes; (void)n_in; (void)out_size;
    const float* blobs = (const float*)d_in[0];
    float* out = (float*)d_out;

    dim3 grid(RES / TILE_X, RES / TILE_Y, NSPLIT);  // 16 x 32 tiles x 4 quarters
    dim3 block(BXD, BYD);
    splat_render_kernel<<<grid, block>>>(blobs, out);
}

// round 16
// speedup vs baseline: 1.4931x; 1.0992x over previous
#include <cuda_runtime.h>

#define RES 512
#define NBLOBS 2048
#define NSPLIT 4
#define QUART (NBLOBS / NSPLIT)
#define TILE_X 32
#define TILE_Y 16
#define BXD 32
#define BYD 4
#define NT 128           // threads per CTA
#define PPT 4            // pixels per thread (stride BYD rows)
#define QCUT 3.3f        // cutoff in sigma units; exp(-5.445) ~ 4.3e-3
#define QCUT2 (QCUT * QCUT)
#define NPIX (RES * RES * 3)
#define NTILES ((RES / TILE_X) * (RES / TILE_Y))

// Scratch (no allocations allowed): partial images + per-tile arrival counters.
__device__ float g_part[NSPLIT][NPIX];
__device__ unsigned int g_cnt[NTILES];   // zero-init at load; reset by last arriver

// Packed f32x2 helpers (FFMA2 path — ptxas never emits this from C++).
#define FMA2(acc, g, c) \
    asm("fma.rn.f32x2 %0, %1, %2, %0;" : "+l"(acc) : "l"(g), "l"(c))
#define PACK2(out, lo, hi) \
    asm("mov.b64 %0, {%1, %2};" : "=l"(out) : "f"(lo), "f"(hi))
#define UNPACK2(lo, hi, in) \
    asm("mov.b64 {%0, %1}, %2;" : "=f"(lo), "=f"(hi) : "l"(in))
#define EX2(out, in) \
    asm("ex2.approx.ftz.f32 %0, %1;" : "=f"(out) : "f"(in))

// ---------------------------------------------------------------------------
// Render: one CTA per (32x16 tile, blob-quarter). 128 threads; 4 px/thread.
// Per-batch: prefetch raw blob (2 float4), derive splat constants in-register,
// cull via exact disk-vs-box test in the blob's whitened (a,b) frame,
// ballot/prefix-compact survivors into shared, evaluate 2-way-unrolled with a
// MULTIPLICATIVE Gaussian recurrence along each thread's y-column:
//   a = A*px + B*py + P,  b = C*px + D*py + Q   (P,Q fold in the blob center)
//   g(0) = 2^t0, u(0) = 2^d0, g(k+1) = g(k)*u(k), u(k+1) = u(k)*w,  w = 2^dd
// (t<=0 always and the 4-pixel log2-span is < 70, so no under/overflow), with
// f32x2-packed RGB accumulation.
// Tail: last-arriver CTA per tile fuses the four partials and writes out.
// ---------------------------------------------------------------------------
__global__ void __launch_bounds__(NT, 8) splat_render_kernel(
        const float* __restrict__ blobs, float* __restrict__ out) {
    __shared__ float4 sP[NT][4];
    __shared__ int sWarp[NT / 32];
    __shared__ unsigned int sArrive;

    const int tx = threadIdx.x;            // 0..31
    const int ty = threadIdx.y;            // 0..3
    const int tid = ty * BXD + tx;
    const int lane = tid & 31;
    const int wid = tid >> 5;
    const int z = blockIdx.z;
    const int blobBase = z * QUART;
    const int tile = blockIdx.y * gridDim.x + blockIdx.x;

    const int x = blockIdx.x * TILE_X + tx;
    const int y0 = blockIdx.y * TILE_Y + ty;
    const float inv = 1.0f / (float)RES;
    const float px = ((float)x + 0.5f) * inv;
    const float py = ((float)y0 + 0.5f) * inv;

    // Tile center and half-extents in normalized coords.
    const float hx = 0.5f * (float)TILE_X * inv;
    const float hy = 0.5f * (float)TILE_Y * inv;
    const float tcx = (float)blockIdx.x * ((float)TILE_X * inv) + hx;
    const float tcy = (float)blockIdx.y * ((float)TILE_Y * inv) + hy;

    // Packed accumulators: (k0,k1) and (k2,k3) pixel pairs for R,G,B.
    unsigned long long accR01 = 0ull, accR23 = 0ull;
    unsigned long long accG01 = 0ull, accG23 = 0ull;
    unsigned long long accB01 = 0ull, accB23 = 0ull;

    // Prefetch batch 0 raw blob (8 floats).
    const float4* __restrict__ blobs4 = (const float4*)blobs;
    float4 r0 = blobs4[(blobBase + tid) * 2 + 0];
    float4 r1 = blobs4[(blobBase + tid) * 2 + 1];

    for (int base = 0; base < QUART; base += NT) {
        // Derive splat constants for this thread's blob of the current batch.
        const float bx = r0.x, by = r0.y, sx = r0.z, sy = r0.w;
        const float rot = r1.x;
        float s, c;
        __sincosf(rot, &s, &c);
        const float kk = 0.84932180f;                  // sqrt(0.5*log2(e))
        const float isx = __fdividef(kk, sx);
        const float isy = __fdividef(kk, sy);
        const float A = c * isx, B = s * isx;
        const float C = -s * isy, D = c * isy;
        const float P = -fmaf(A, bx, B * by);          // fold center into offset
        const float Q = -fmaf(C, bx, D * by);
        const float dlt = (float)BYD * inv;
        const float da_ = B * dlt, db_ = D * dlt;
        const float m1 = -2.0f * da_, m2 = -2.0f * db_;
        const float c0 = -(da_ * da_ + db_ * db_);
        float w;                                       // w = 2^(2*c0)
        EX2(w, c0 + c0);

        // Cull: tile -> interval box in (a,b); keep iff the box intersects the
        // disk a^2+b^2 <= (QCUT*kk)^2 (a,b carry the kk factor).
        const float ac = fmaf(A, tcx, fmaf(B, tcy, P));
        const float bc = fmaf(C, tcx, fmaf(D, tcy, Q));
        const float ra = fabsf(A) * hx + fabsf(B) * hy;
        const float rb = fabsf(C) * hx + fabsf(D) * hy;
        const float dA = fmaxf(fabsf(ac) - ra, 0.0f);
        const float dB = fmaxf(fabsf(bc) - rb, 0.0f);
        const float rad2 = QCUT2 * (kk * kk);
        const bool keep = fmaf(dA, dA, dB * dB) <= rad2;

        const unsigned m = __ballot_sync(0xffffffffu, keep);
        if (lane == 0) sWarp[wid] = __popc(m);
        __syncthreads();

        int off = 0, total = 0;
#pragma unroll
        for (int w2 = 0; w2 < NT / 32; ++w2) {
            int cw = sWarp[w2];
            if (w2 < wid) off += cw;
            total += cw;
        }

        if (keep) {
            const int slot = off + __popc(m & ((1u << lane) - 1u));
            sP[slot][0] = make_float4(A, B, C, D);
            sP[slot][1] = make_float4(P, Q, m1, m2);
            sP[slot][2] = make_float4(r1.y, r1.y, r1.z, r1.z);       // (r,r,g,g)
            sP[slot][3] = make_float4(r1.w, r1.w, c0, w);            // (b,b,c0,w)
        }
        __syncthreads();

        // Prefetch next batch's raw blob (latency hidden behind the j-loop).
        const int nb = base + NT;
        if (nb < QUART) {
            const int i2 = blobBase + nb + tid;
            r0 = blobs4[i2 * 2 + 0];
            r1 = blobs4[i2 * 2 + 1];
        }

#define PAIR_BODY(J)                                                          \
        {                                                                     \
            const float4 p0 = sP[(J)][0];                                     \
            const float4 p1 = sP[(J)][1];                                     \
            const ulonglong2 pc =                                             \
                *reinterpret_cast<const ulonglong2*>(&sP[(J)][2]);            \
            const ulonglong2 q3 =                                             \
                *reinterpret_cast<const ulonglong2*>(&sP[(J)][3]);            \
            float c0f, wf;                                                    \
            UNPACK2(c0f, wf, q3.y);                                           \
            float a = fmaf(p0.x, px, fmaf(p0.y, py, p1.x));                   \
            float b = fmaf(p0.z, px, fmaf(p0.w, py, p1.y));                   \
            float t = fmaf(a, -a, -b * b);                                    \
            float d = fmaf(a, p1.z, fmaf(b, p1.w, c0f));                      \
            float g0, u0;                                                     \
            EX2(g0, t);                                                       \
            EX2(u0, d);                                                       \
            const float g1 = g0 * u0;                                         \
            const float u1 = u0 * wf;                                         \
            const float g2 = g1 * u1;                                         \
            const float u2 = u1 * wf;                                         \
            const float g3 = g2 * u2;                                         \
            unsigned long long G01, G23;                                      \
            PACK2(G01, g0, g1);                                               \
            PACK2(G23, g2, g3);                                               \
            FMA2(accR01, G01, pc.x);                                          \
            FMA2(accR23, G23, pc.x);                                          \
            FMA2(accG01, G01, pc.y);                                          \
            FMA2(accG23, G23, pc.y);                                          \
            FMA2(accB01, G01, q3.x);                                          \
            FMA2(accB23, G23, q3.x);                                          \
        }

        int j = 0;
        for (; j + 2 <= total; j += 2) {
            PAIR_BODY(j)
            PAIR_BODY(j + 1)
        }
        if (j < total) {
            PAIR_BODY(j)
        }
#undef PAIR_BODY

        __syncthreads();  // protect sP / sWarp before next batch rewrites them
    }

    // Unpack accumulators.
    float aR[PPT], aG[PPT], aB[PPT];
    UNPACK2(aR[0], aR[1], accR01);
    UNPACK2(aR[2], aR[3], accR23);
    UNPACK2(aG[0], aG[1], accG01);
    UNPACK2(aG[2], aG[3], accG23);
    UNPACK2(aB[0], aB[1], accB01);
    UNPACK2(aB[2], aB[3], accB23);

    // ---- Fused combine (last-block pattern, no spin; deadlock-free) ----
    {
        int idx = (y0 * RES + x) * 3;
        float* __restrict__ mine = g_part[z];
#pragma unroll
        for (int k = 0; k < PPT; ++k) {
            mine[idx + 0] = aR[k];
            mine[idx + 1] = aG[k];
            mine[idx + 2] = aB[k];
            idx += BYD * RES * 3;
        }
    }
    __threadfence();
    __syncthreads();
    if (tid == 0) sArrive = atomicAdd(&g_cnt[tile], 1u);
    __syncthreads();
    if (sArrive == NSPLIT - 1u) {
        // We are last: all peers' partials are published (L2-resident).
        __threadfence();   // acquire: order peers' data before our reads
        const float* __restrict__ pA = g_part[(z + 1) & (NSPLIT - 1)];
        const float* __restrict__ pB = g_part[(z + 2) & (NSPLIT - 1)];
        const float* __restrict__ pC = g_part[(z + 3) & (NSPLIT - 1)];
        int idx = (y0 * RES + x) * 3;
#pragma unroll
        for (int k = 0; k < PPT; ++k) {
            out[idx + 0] = aR[k] + pA[idx + 0] + (pB[idx + 0] + pC[idx + 0]);
            out[idx + 1] = aG[k] + pA[idx + 1] + (pB[idx + 1] + pC[idx + 1]);
            out[idx + 2] = aB[k] + pA[idx + 2] + (pB[idx + 2] + pC[idx + 2]);
            idx += BYD * RES * 3;
        }
        __syncthreads();
        if (tid == 0) g_cnt[tile] = 0u;    // reset for next graph replay
    }
}

extern "C" void kernel_launch(void* const* d_in, const int* in_sizes, int n_in,
                              void* d_out, int out_size) {
    (void)in_sizes; (void)n_in; (void)out_size;
    const float* blobs = (const float*)d_in[0];
    float* out = (float*)d_out;

    dim3 grid(RES / TILE_X, RES / TILE_Y, NSPLIT);  // 16 x 32 tiles x 4 quarters
    dim3 block(BXD, BYD);
    splat_render_kernel<<<grid, block>>>(blobs, out);
}